// round 13
// baseline (speedup 1.0000x reference)
#include <cuda_runtime.h>
#include <cuda_fp16.h>
#include <cstdint>

// ============================================================
// FFTEmbedding as implicit-im2col GEMM (sm_100 legacy-HMMA path)
//   out = A(131072x256 Toeplitz windows) @ WeffT(512x256)^T + bias
// R13 = R11 with ALL cross-warp coupling removed: each warp owns a
//   private double-buffered 384-float x-segment, prefetched via
//   cp.async (zfill-predicated). No mbarrier, no CTA barrier in the
//   loop — warps drift freely; per-iter sync = wait_all + syncwarp.
// ============================================================

#define B_SZ   16
#define T_SZ   8192
#define W_SZ   256
#define EMB    512
#define NFEAT  258

#define BM 128
#define BN 64                 // CTA n-tile
#define MTILES 1024           // (B*T)/BM
#define NGROUPS 8             // EMB/BN
#define GRID   592            // 4 CTAs per SM
#define CTAS_PER_N 74         // GRID / NGROUPS
#define THREADS 128

#define PB 264                // B smem pitch in halfs (256 + 8 pad)
#define SMEM_B_BYTES (64 * PB * 2)             // 33792
#define OFF_SEG   SMEM_B_BYTES
// seg[4 warps][2 bufs][384 floats] = 12288 B
#define SMEM_TOTAL (OFF_SEG + 4 * 2 * 384 * 4)

// fp16 Weff^T, [EMB][W_SZ]
__device__ __half g_weffT[EMB * W_SZ];

__device__ __forceinline__ uint32_t smem_to_u32(const void* p) {
    uint32_t a;
    asm("{ .reg .u64 t; cvta.to.shared.u64 t, %1; cvt.u32.u64 %0, t; }" : "=r"(a) : "l"(p));
    return a;
}

__device__ __forceinline__ uint32_t ldcvt(const float* s) {
    __half2 h = __floats2half2_rn(s[0], s[1]);
    return *reinterpret_cast<uint32_t*>(&h);
}

__device__ __forceinline__ void cp_async4(uint32_t dst, const float* src, int sz) {
    asm volatile("cp.async.ca.shared.global [%0], [%1], 4, %2;"
                 :: "r"(dst), "l"(src), "r"(sz) : "memory");
}

__device__ __forceinline__ void cp_async_wait_all() {
    asm volatile("cp.async.wait_all;" ::: "memory");
}

__device__ __forceinline__ void mma16816(float* c, uint32_t a0, uint32_t a1,
                                         uint32_t a2, uint32_t a3,
                                         uint32_t b0, uint32_t b1) {
    asm volatile(
        "mma.sync.aligned.m16n8k16.row.col.f32.f16.f16.f32 "
        "{%0,%1,%2,%3}, {%4,%5,%6,%7}, {%8,%9}, {%0,%1,%2,%3};"
        : "+f"(c[0]), "+f"(c[1]), "+f"(c[2]), "+f"(c[3])
        : "r"(a0), "r"(a1), "r"(a2), "r"(a3), "r"(b0), "r"(b1));
}

__device__ __forceinline__ void ldmatrix_x4(uint32_t& r0, uint32_t& r1,
                                            uint32_t& r2, uint32_t& r3, uint32_t addr) {
    asm volatile("ldmatrix.sync.aligned.m8n8.x4.shared.b16 {%0,%1,%2,%3}, [%4];"
                 : "=r"(r0), "=r"(r1), "=r"(r2), "=r"(r3) : "r"(addr));
}

// Column permutation within each warp's 16-col slice (enables STG.128).
__device__ __host__ __forceinline__ int permcol(int s) {
    return (s < 8) ? ((s & 1) ? 2 * s - 1 : 2 * s)
                   : ((s & 1) ? 2 * s - 15 : 2 * s - 14);
}

// ============================================================
// Kernel 1: Weff^T precompute (angle recurrence)
// ============================================================
__global__ void weff_kernel(const float* __restrict__ weight) {
    __shared__ float w1[129], w2[129];
    const int e = blockIdx.x;
    for (int f = threadIdx.x; f < NFEAT; f += 256) {
        float v = weight[e * NFEAT + f];
        if (f < 129) w1[f] = v; else w2[f - 129] = v;
    }
    __syncthreads();
    const int n = threadIdx.x;                // k position 0..255
    float s1, c1;
    sincospif((float)n / 128.0f, &s1, &c1);   // step angle 2*pi*n/256
    float acc = w1[0];
    float c = c1, s = s1;
    #pragma unroll 4
    for (int kk = 1; kk <= 128; kk++) {
        acc = fmaf(c, w1[kk], acc);
        acc = fmaf(-s, w2[kk], acc);
        float cn = fmaf(c, c1, -s * s1);
        float sn = fmaf(s, c1,  c * s1);
        c = cn; s = sn;
    }
    g_weffT[e * W_SZ + n] = __float2half_rn(acc);
}

// ============================================================
// Kernel 2: persistent GEMM, grid=592 (4 CTAs/SM), 128 threads
// warp tile: 128m x 16n; per-warp private segments, zero cross-warp sync
// ============================================================
__global__ void __launch_bounds__(THREADS, 4) fft_gemm_kernel(
    const float* __restrict__ x,
    const float* __restrict__ bias,
    float* __restrict__ out)
{
    extern __shared__ char smem[];
    __half* Bs = (__half*)smem;
    // seg[warp][buf][384]
    float (*seg)[2][384] = (float(*)[2][384])(smem + OFF_SEG);

    const int tid  = threadIdx.x;
    const int wid  = tid >> 5;
    const int lane = tid & 31;
    const int q    = lane & 3;
    const int r4   = lane >> 2;
    const int ng   = (int)(blockIdx.x & (NGROUPS - 1));
    const int e0   = ng * BN;

    // ---- load B tile (WeffT rows e0..e0+63), permuted within slices ----
    for (int u = tid; u < 2048; u += THREADS) {
        int r  = u >> 5;          // Bs row 0..63
        int ch = u & 31;          // 16B chunk along k
        int esrc = e0 + (r & ~15) + permcol(r & 15);
        uint4 v = *reinterpret_cast<const uint4*>(&g_weffT[esrc * W_SZ + ch * 8]);
        *reinterpret_cast<uint4*>(Bs + r * PB + ch * 8) = v;
    }

    // ---- per-thread bias: 4 contiguous cols ----
    const int colb = e0 + wid * 16 + 4 * q;
    const float4 bias4 = *reinterpret_cast<const float4*>(bias + colb);

    // ---- ldmatrix base address for this warp's 16-row B slice ----
    const uint32_t sbB = smem_to_u32(Bs);
    const int brow = wid * 16 + (lane & 7) + ((lane & 16) ? 8 : 0);
    const int bkof = (lane & 8) ? 8 : 0;
    const uint32_t baddr0 = sbB + (uint32_t)(brow * PB + bkof) * 2u;

    // per-warp segment SMEM base addresses (for cp.async dst)
    const uint32_t segaddr[2] = { smem_to_u32(&seg[wid][0][0]),
                                  smem_to_u32(&seg[wid][1][0]) };

    // ---- initial segment load for first M-tile (this warp only) ----
    const int mt0 = (int)(blockIdx.x >> 3);
    {
        int bidx = mt0 >> 6, t0 = (mt0 & 63) * BM;
        const float* xb = x + bidx * T_SZ;
        #pragma unroll
        for (int c = 0; c < 12; c++) {
            int j = lane + 32 * c;
            int gx = t0 + j - (W_SZ - 1);
            float v = (j < 383 && gx >= 0) ? xb[gx] : 0.0f;
            seg[wid][0][j] = v;
        }
        __syncwarp();
    }
    __syncthreads();   // B tile visible to all warps

    int pb = 0;
    for (int mt = mt0; mt < MTILES; mt += CTAS_PER_N, pb ^= 1) {
        // ---- cp.async prefetch of next segment into this warp's alt buf ----
        const int mtn = mt + CTAS_PER_N;
        if (mtn < MTILES) {
            int bidx = mtn >> 6, t0 = (mtn & 63) * BM;
            const float* xb = x + bidx * T_SZ;
            #pragma unroll
            for (int c = 0; c < 12; c++) {
                int j = lane + 32 * c;
                int gx = t0 + j - (W_SZ - 1);
                int sz = (j < 383 && gx >= 0) ? 4 : 0;
                cp_async4(segaddr[pb ^ 1] + (uint32_t)(j * 4),
                          xb + (gx >= 0 ? gx : 0), sz);
            }
        }

        // ---- accumulators initialized with bias ----
        float acc[8][2][4];
        #pragma unroll
        for (int m = 0; m < 8; m++) {
            acc[m][0][0] = bias4.x; acc[m][0][1] = bias4.y;
            acc[m][0][2] = bias4.x; acc[m][0][3] = bias4.y;
            acc[m][1][0] = bias4.z; acc[m][1][1] = bias4.w;
            acc[m][1][2] = bias4.z; acc[m][1][3] = bias4.w;
        }

        const float* sg = seg[wid][pb];
        const int base0 = r4 + 2 * q;

        // Toeplitz A: av[j] = half2(seg[base0 + 16*ks + 8j .. +1])
        uint32_t av[17];
        #pragma unroll
        for (int j = 0; j < 17; j++) av[j] = ldcvt(sg + base0 + 8 * j);

        #pragma unroll
        for (int ks = 0; ks < 16; ks++) {
            uint32_t b0, b1, b2, b3;
            ldmatrix_x4(b0, b1, b2, b3, baddr0 + (uint32_t)(ks * 32));
            #pragma unroll
            for (int m = 0; m < 8; m++) {
                mma16816(acc[m][0], av[2*m], av[2*m+1], av[2*m+1], av[2*m+2], b0, b1);
                mma16816(acc[m][1], av[2*m], av[2*m+1], av[2*m+1], av[2*m+2], b2, b3);
            }
            if (ks < 15) {
                #pragma unroll
                for (int j = 0; j < 15; j++) av[j] = av[j + 2];
                av[15] = ldcvt(sg + base0 + 16 * (ks + 1) + 120);
                av[16] = ldcvt(sg + base0 + 16 * (ks + 1) + 128);
            }
        }

        // ---- epilogue: STG.128 (permuted cols contiguous, bias pre-added) ----
        const size_t rowb = (size_t)mt * BM + (size_t)r4;
        #pragma unroll
        for (int m = 0; m < 8; m++) {
            float* o0 = out + (rowb + 16 * m) * EMB + colb;
            float* o1 = o0 + 8 * EMB;
            float4 v0 = make_float4(acc[m][0][0], acc[m][0][1],
                                    acc[m][1][0], acc[m][1][1]);
            float4 v1 = make_float4(acc[m][0][2], acc[m][0][3],
                                    acc[m][1][2], acc[m][1][3]);
            *reinterpret_cast<float4*>(o0) = v0;
            *reinterpret_cast<float4*>(o1) = v1;
        }

        // ---- per-warp sync only: prefetch done, buffer swap safe ----
        if (mtn < MTILES) {
            cp_async_wait_all();
            __syncwarp();
        }
    }
}

// ============================================================
extern "C" void kernel_launch(void* const* d_in, const int* in_sizes, int n_in,
                              void* d_out, int out_size) {
    const float* x  = nullptr;
    const float* wt = nullptr;
    const float* bs = nullptr;
    for (int i = 0; i < n_in; i++) {
        if (in_sizes[i] == B_SZ * T_SZ)        x  = (const float*)d_in[i];
        else if (in_sizes[i] == EMB * NFEAT)   wt = (const float*)d_in[i];
        else if (in_sizes[i] == EMB)           bs = (const float*)d_in[i];
    }

    weff_kernel<<<EMB, 256>>>(wt);

    cudaFuncSetAttribute(fft_gemm_kernel,
                         cudaFuncAttributeMaxDynamicSharedMemorySize, SMEM_TOTAL);
    fft_gemm_kernel<<<GRID, THREADS, SMEM_TOTAL>>>(x, bs, (float*)d_out);
}

// round 14
// speedup vs baseline: 1.0932x; 1.0932x over previous
#include <cuda_runtime.h>
#include <cuda_fp16.h>
#include <cstdint>

// ============================================================
// FFTEmbedding as implicit-im2col GEMM (sm_100 legacy-HMMA path)
//   out = A(131072x256 Toeplitz windows) @ WeffT(512x256)^T + bias
// R14 = R12 minus stagger (proven no-op), plus bias injected as the
//   mma C-operand on the first k-step (D = A*B + bias) — deletes the
//   64-MOV accumulator-init block from every warp-iteration.
// ============================================================

#define B_SZ   16
#define T_SZ   8192
#define W_SZ   256
#define EMB    512
#define NFEAT  258

#define BM 128
#define BN 64                 // CTA n-tile
#define MTILES 1024           // (B*T)/BM
#define NGROUPS 8             // EMB/BN
#define GRID   592            // 4 CTAs per SM
#define CTAS_PER_N 74         // GRID / NGROUPS
#define THREADS 128

#define PB 264                // B smem pitch in halfs (256 + 8 pad)
#define SMEM_B_BYTES (64 * PB * 2)             // 33792
#define OFF_MBAR  SMEM_B_BYTES                 // 8 bytes + 8 pad
#define OFF_SEG   (SMEM_B_BYTES + 16)
#define SMEM_TOTAL (OFF_SEG + 2 * 384 * 4)

// fp16 Weff^T, [EMB][W_SZ]
__device__ __half g_weffT[EMB * W_SZ];

__device__ __forceinline__ uint32_t smem_to_u32(const void* p) {
    uint32_t a;
    asm("{ .reg .u64 t; cvta.to.shared.u64 t, %1; cvt.u32.u64 %0, t; }" : "=r"(a) : "l"(p));
    return a;
}

__device__ __forceinline__ uint32_t ldcvt(const float* s) {
    __half2 h = __floats2half2_rn(s[0], s[1]);
    return *reinterpret_cast<uint32_t*>(&h);
}

// D = A*B + D   (accumulate in place)
__device__ __forceinline__ void mma16816(float* c, uint32_t a0, uint32_t a1,
                                         uint32_t a2, uint32_t a3,
                                         uint32_t b0, uint32_t b1) {
    asm volatile(
        "mma.sync.aligned.m16n8k16.row.col.f32.f16.f16.f32 "
        "{%0,%1,%2,%3}, {%4,%5,%6,%7}, {%8,%9}, {%0,%1,%2,%3};"
        : "+f"(c[0]), "+f"(c[1]), "+f"(c[2]), "+f"(c[3])
        : "r"(a0), "r"(a1), "r"(a2), "r"(a3), "r"(b0), "r"(b1));
}

// D = A*B + {cx,cy,cx,cy}   (first k-step: bias injected via C operand)
__device__ __forceinline__ void mma16816_init(float* d, uint32_t a0, uint32_t a1,
                                              uint32_t a2, uint32_t a3,
                                              uint32_t b0, uint32_t b1,
                                              float cx, float cy) {
    asm volatile(
        "mma.sync.aligned.m16n8k16.row.col.f32.f16.f16.f32 "
        "{%0,%1,%2,%3}, {%4,%5,%6,%7}, {%8,%9}, {%10,%11,%10,%11};"
        : "=f"(d[0]), "=f"(d[1]), "=f"(d[2]), "=f"(d[3])
        : "r"(a0), "r"(a1), "r"(a2), "r"(a3), "r"(b0), "r"(b1),
          "f"(cx), "f"(cy));
}

__device__ __forceinline__ void ldmatrix_x4(uint32_t& r0, uint32_t& r1,
                                            uint32_t& r2, uint32_t& r3, uint32_t addr) {
    asm volatile("ldmatrix.sync.aligned.m8n8.x4.shared.b16 {%0,%1,%2,%3}, [%4];"
                 : "=r"(r0), "=r"(r1), "=r"(r2), "=r"(r3) : "r"(addr));
}

#define MBARRIER_INIT(addr, count) \
    asm volatile("mbarrier.init.shared.b64 [%0], %1;" \
        :: "r"((uint32_t)(addr)), "r"((uint32_t)(count)) : "memory")

#define MBARRIER_ARRIVE(addr) \
    asm volatile("mbarrier.arrive.release.cta.shared.b64 _, [%0];" \
        :: "r"((uint32_t)(addr)) : "memory")

#define MBARRIER_WAIT_PARITY(mbar_smem_addr, phase_parity) do { \
    uint32_t _mbar = (uint32_t)(mbar_smem_addr); \
    uint32_t _parity = (uint32_t)(phase_parity); \
    uint32_t _done; \
    asm volatile( \
        "{\n\t.reg .pred p;\n\t" \
        "mbarrier.try_wait.parity.acquire.cta.shared::cta.b64 p, [%1], %2;\n\t" \
        "selp.b32 %0, 1, 0, p;\n\t}" \
        : "=r"(_done) : "r"(_mbar), "r"(_parity) : "memory"); \
    if (!_done) { \
        asm volatile( \
            "{\n\t.reg .pred P1;\n\t" \
            "WAIT_LOOP_%=:\n\t" \
            "mbarrier.try_wait.parity.acquire.cta.shared::cta.b64 P1, [%0], %1, 0x989680;\n\t" \
            "@P1 bra.uni WAIT_DONE_%=;\n\t" \
            "bra.uni WAIT_LOOP_%=;\n\t" \
            "WAIT_DONE_%=:\n\t}" \
            :: "r"(_mbar), "r"(_parity) : "memory"); \
    } \
} while(0)

// Column permutation within each warp's 16-col slice (enables STG.128).
__device__ __host__ __forceinline__ int permcol(int s) {
    return (s < 8) ? ((s & 1) ? 2 * s - 1 : 2 * s)
                   : ((s & 1) ? 2 * s - 15 : 2 * s - 14);
}

// ============================================================
// Kernel 1: Weff^T precompute (angle recurrence)
// ============================================================
__global__ void weff_kernel(const float* __restrict__ weight) {
    __shared__ float w1[129], w2[129];
    const int e = blockIdx.x;
    for (int f = threadIdx.x; f < NFEAT; f += 256) {
        float v = weight[e * NFEAT + f];
        if (f < 129) w1[f] = v; else w2[f - 129] = v;
    }
    __syncthreads();
    const int n = threadIdx.x;                // k position 0..255
    float s1, c1;
    sincospif((float)n / 128.0f, &s1, &c1);   // step angle 2*pi*n/256
    float acc = w1[0];
    float c = c1, s = s1;
    #pragma unroll 4
    for (int kk = 1; kk <= 128; kk++) {
        acc = fmaf(c, w1[kk], acc);
        acc = fmaf(-s, w2[kk], acc);
        float cn = fmaf(c, c1, -s * s1);
        float sn = fmaf(s, c1,  c * s1);
        c = cn; s = sn;
    }
    g_weffT[e * W_SZ + n] = __float2half_rn(acc);
}

// ============================================================
// Kernel 2: persistent GEMM, grid=592 (4 CTAs/SM), 128 threads
// warp tile: 128m x 16n; split-phase mbarrier per iteration
// ============================================================
__global__ void __launch_bounds__(THREADS, 4) fft_gemm_kernel(
    const float* __restrict__ x,
    const float* __restrict__ bias,
    float* __restrict__ out)
{
    extern __shared__ char smem[];
    __half* Bs = (__half*)smem;
    float (*seg)[384] = (float(*)[384])(smem + OFF_SEG);
    const uint32_t sb = smem_to_u32(smem);
    const uint32_t mbar = sb + OFF_MBAR;

    const int tid  = threadIdx.x;
    const int wid  = tid >> 5;
    const int lane = tid & 31;
    const int q    = lane & 3;
    const int r4   = lane >> 2;
    const int ng   = (int)(blockIdx.x & (NGROUPS - 1));
    const int e0   = ng * BN;

    if (tid == 0) MBARRIER_INIT(mbar, THREADS);

    // ---- load B tile (WeffT rows e0..e0+63), permuted within slices ----
    for (int u = tid; u < 2048; u += THREADS) {
        int r  = u >> 5;          // Bs row 0..63
        int ch = u & 31;          // 16B chunk along k
        int esrc = e0 + (r & ~15) + permcol(r & 15);
        uint4 v = *reinterpret_cast<const uint4*>(&g_weffT[esrc * W_SZ + ch * 8]);
        *reinterpret_cast<uint4*>(Bs + r * PB + ch * 8) = v;
    }

    // ---- per-thread bias: 4 contiguous cols ----
    const int colb = e0 + wid * 16 + 4 * q;
    const float4 bias4 = *reinterpret_cast<const float4*>(bias + colb);

    // ---- ldmatrix base address for this warp's 16-row B slice ----
    const uint32_t sbB = smem_to_u32(Bs);
    const int brow = wid * 16 + (lane & 7) + ((lane & 16) ? 8 : 0);
    const int bkof = (lane & 8) ? 8 : 0;
    const uint32_t baddr0 = sbB + (uint32_t)(brow * PB + bkof) * 2u;

    // ---- initial segment load for first M-tile (383 floats, 128 thr) ----
    const int mt0 = (int)(blockIdx.x >> 3);
    {
        int bidx = mt0 >> 6, t0 = (mt0 & 63) * BM;
        const float* xb = x + bidx * T_SZ;
        #pragma unroll
        for (int c = 0; c < 3; c++) {
            int j = tid + c * 128;
            int gx = t0 + j - (W_SZ - 1);
            if (j < 383) seg[0][j] = (gx >= 0) ? xb[gx] : 0.0f;
        }
    }
    __syncthreads();   // B tile + seg[0] + mbarrier init visible

    int pb = 0, ph = 0;
    for (int mt = mt0; mt < MTILES; mt += CTAS_PER_N, pb ^= 1) {
        // ---- prefetch next segment into registers (all loads guarded) ----
        const int mtn = mt + CTAS_PER_N;
        float p0 = 0.0f, p1 = 0.0f, p2 = 0.0f;
        if (mtn < MTILES) {
            int bidx = mtn >> 6, t0 = (mtn & 63) * BM;
            const float* xb = x + bidx * T_SZ;
            int g0 = t0 + tid - (W_SZ - 1);
            int g1 = g0 + 128;
            int g2 = g0 + 256;
            if (g0 >= 0) p0 = xb[g0];
            if (g1 >= 0) p1 = xb[g1];
            if (tid < 127 && g2 >= 0) p2 = xb[g2];
        }

        float acc[8][2][4];
        const float* sg = seg[pb];
        const int base0 = r4 + 2 * q;

        // Toeplitz A: av[j] = half2(seg[base0 + 16*ks + 8j .. +1])
        uint32_t av[17];
        #pragma unroll
        for (int j = 0; j < 17; j++) av[j] = ldcvt(sg + base0 + 8 * j);

        // ---- k-step 0: D = A*B + bias (C operand) — no acc init MOVs ----
        {
            uint32_t b0, b1, b2, b3;
            ldmatrix_x4(b0, b1, b2, b3, baddr0);
            #pragma unroll
            for (int m = 0; m < 8; m++) {
                mma16816_init(acc[m][0], av[2*m], av[2*m+1], av[2*m+1], av[2*m+2],
                              b0, b1, bias4.x, bias4.y);
                mma16816_init(acc[m][1], av[2*m], av[2*m+1], av[2*m+1], av[2*m+2],
                              b2, b3, bias4.z, bias4.w);
            }
            #pragma unroll
            for (int j = 0; j < 15; j++) av[j] = av[j + 2];
            av[15] = ldcvt(sg + base0 + 16 + 120);
            av[16] = ldcvt(sg + base0 + 16 + 128);
        }

        // ---- k-steps 1..15: accumulate ----
        #pragma unroll
        for (int ks = 1; ks < 16; ks++) {
            uint32_t b0, b1, b2, b3;
            ldmatrix_x4(b0, b1, b2, b3, baddr0 + (uint32_t)(ks * 32));
            #pragma unroll
            for (int m = 0; m < 8; m++) {
                mma16816(acc[m][0], av[2*m], av[2*m+1], av[2*m+1], av[2*m+2], b0, b1);
                mma16816(acc[m][1], av[2*m], av[2*m+1], av[2*m+1], av[2*m+2], b2, b3);
            }
            if (ks < 15) {
                #pragma unroll
                for (int j = 0; j < 15; j++) av[j] = av[j + 2];
                av[15] = ldcvt(sg + base0 + 16 * (ks + 1) + 120);
                av[16] = ldcvt(sg + base0 + 16 * (ks + 1) + 128);
            }
        }

        // ---- store prefetched segment, then ARRIVE (mainloop reads done) ----
        if (mtn < MTILES) {
            seg[pb ^ 1][tid] = p0;
            seg[pb ^ 1][tid + 128] = p1;
            if (tid < 127) seg[pb ^ 1][tid + 256] = p2;
            MBARRIER_ARRIVE(mbar);
        }

        // ---- epilogue (outside critical path): STG.128, bias pre-added ----
        const size_t rowb = (size_t)mt * BM + (size_t)r4;
        #pragma unroll
        for (int m = 0; m < 8; m++) {
            float* o0 = out + (rowb + 16 * m) * EMB + colb;
            float* o1 = o0 + 8 * EMB;
            float4 v0 = make_float4(acc[m][0][0], acc[m][0][1],
                                    acc[m][1][0], acc[m][1][1]);
            float4 v1 = make_float4(acc[m][0][2], acc[m][0][3],
                                    acc[m][1][2], acc[m][1][3]);
            *reinterpret_cast<float4*>(o0) = v0;
            *reinterpret_cast<float4*>(o1) = v1;
        }

        // ---- wait for all warps' arrivals before next mainloop ----
        if (mtn < MTILES) {
            MBARRIER_WAIT_PARITY(mbar, ph);
            ph ^= 1;
        }
    }
}

// ============================================================
extern "C" void kernel_launch(void* const* d_in, const int* in_sizes, int n_in,
                              void* d_out, int out_size) {
    const float* x  = nullptr;
    const float* wt = nullptr;
    const float* bs = nullptr;
    for (int i = 0; i < n_in; i++) {
        if (in_sizes[i] == B_SZ * T_SZ)        x  = (const float*)d_in[i];
        else if (in_sizes[i] == EMB * NFEAT)   wt = (const float*)d_in[i];
        else if (in_sizes[i] == EMB)           bs = (const float*)d_in[i];
    }

    weff_kernel<<<EMB, 256>>>(wt);

    cudaFuncSetAttribute(fft_gemm_kernel,
                         cudaFuncAttributeMaxDynamicSharedMemorySize, SMEM_TOTAL);
    fft_gemm_kernel<<<GRID, THREADS, SMEM_TOTAL>>>(x, bs, (float*)d_out);
}

// round 15
// speedup vs baseline: 1.0997x; 1.0059x over previous
#include <cuda_runtime.h>
#include <cuda_fp16.h>
#include <cstdint>

// ============================================================
// FFTEmbedding as implicit-im2col GEMM (sm_100 legacy-HMMA path)
//   out = A(131072x256 Toeplitz windows) @ WeffT(512x256)^T + bias
// R15 = R14 with fp16-ACCUMULATE mma (f16.f16.f16.f16): if the
//   legacy path runs fp16-acc at 2x rate (rt 4 vs 8), tensor busy
//   halves. Bias folds into the packed C operand; epilogue unpacks
//   h2 -> f32. Precision budget: est rel_err 5-8e-4 (< 1e-3).
// ============================================================

#define B_SZ   16
#define T_SZ   8192
#define W_SZ   256
#define EMB    512
#define NFEAT  258

#define BM 128
#define BN 64                 // CTA n-tile
#define MTILES 1024           // (B*T)/BM
#define NGROUPS 8             // EMB/BN
#define GRID   592            // 4 CTAs per SM
#define CTAS_PER_N 74         // GRID / NGROUPS
#define THREADS 128

#define PB 264                // B smem pitch in halfs (256 + 8 pad)
#define SMEM_B_BYTES (64 * PB * 2)             // 33792
#define OFF_MBAR  SMEM_B_BYTES                 // 8 bytes + 8 pad
#define OFF_SEG   (SMEM_B_BYTES + 16)
#define SMEM_TOTAL (OFF_SEG + 2 * 384 * 4)

// fp16 Weff^T, [EMB][W_SZ]
__device__ __half g_weffT[EMB * W_SZ];

__device__ __forceinline__ uint32_t smem_to_u32(const void* p) {
    uint32_t a;
    asm("{ .reg .u64 t; cvta.to.shared.u64 t, %1; cvt.u32.u64 %0, t; }" : "=r"(a) : "l"(p));
    return a;
}

__device__ __forceinline__ uint32_t ldcvt(const float* s) {
    __half2 h = __floats2half2_rn(s[0], s[1]);
    return *reinterpret_cast<uint32_t*>(&h);
}

// fp16-accumulate: D(h2 x2) = A*B + D
__device__ __forceinline__ void mma16816h(uint32_t* c, uint32_t a0, uint32_t a1,
                                          uint32_t a2, uint32_t a3,
                                          uint32_t b0, uint32_t b1) {
    asm volatile(
        "mma.sync.aligned.m16n8k16.row.col.f16.f16.f16.f16 "
        "{%0,%1}, {%2,%3,%4,%5}, {%6,%7}, {%0,%1};"
        : "+r"(c[0]), "+r"(c[1])
        : "r"(a0), "r"(a1), "r"(a2), "r"(a3), "r"(b0), "r"(b1));
}

// fp16-accumulate init: D = A*B + {cb, cb}  (bias pair replicated to both rows)
__device__ __forceinline__ void mma16816h_init(uint32_t* d, uint32_t a0, uint32_t a1,
                                               uint32_t a2, uint32_t a3,
                                               uint32_t b0, uint32_t b1, uint32_t cb) {
    asm volatile(
        "mma.sync.aligned.m16n8k16.row.col.f16.f16.f16.f16 "
        "{%0,%1}, {%2,%3,%4,%5}, {%6,%7}, {%8,%8};"
        : "=r"(d[0]), "=r"(d[1])
        : "r"(a0), "r"(a1), "r"(a2), "r"(a3), "r"(b0), "r"(b1), "r"(cb));
}

__device__ __forceinline__ void ldmatrix_x4(uint32_t& r0, uint32_t& r1,
                                            uint32_t& r2, uint32_t& r3, uint32_t addr) {
    asm volatile("ldmatrix.sync.aligned.m8n8.x4.shared.b16 {%0,%1,%2,%3}, [%4];"
                 : "=r"(r0), "=r"(r1), "=r"(r2), "=r"(r3) : "r"(addr));
}

#define MBARRIER_INIT(addr, count) \
    asm volatile("mbarrier.init.shared.b64 [%0], %1;" \
        :: "r"((uint32_t)(addr)), "r"((uint32_t)(count)) : "memory")

#define MBARRIER_ARRIVE(addr) \
    asm volatile("mbarrier.arrive.release.cta.shared.b64 _, [%0];" \
        :: "r"((uint32_t)(addr)) : "memory")

#define MBARRIER_WAIT_PARITY(mbar_smem_addr, phase_parity) do { \
    uint32_t _mbar = (uint32_t)(mbar_smem_addr); \
    uint32_t _parity = (uint32_t)(phase_parity); \
    uint32_t _done; \
    asm volatile( \
        "{\n\t.reg .pred p;\n\t" \
        "mbarrier.try_wait.parity.acquire.cta.shared::cta.b64 p, [%1], %2;\n\t" \
        "selp.b32 %0, 1, 0, p;\n\t}" \
        : "=r"(_done) : "r"(_mbar), "r"(_parity) : "memory"); \
    if (!_done) { \
        asm volatile( \
            "{\n\t.reg .pred P1;\n\t" \
            "WAIT_LOOP_%=:\n\t" \
            "mbarrier.try_wait.parity.acquire.cta.shared::cta.b64 P1, [%0], %1, 0x989680;\n\t" \
            "@P1 bra.uni WAIT_DONE_%=;\n\t" \
            "bra.uni WAIT_LOOP_%=;\n\t" \
            "WAIT_DONE_%=:\n\t}" \
            :: "r"(_mbar), "r"(_parity) : "memory"); \
    } \
} while(0)

// Column permutation within each warp's 16-col slice (enables STG.128).
__device__ __host__ __forceinline__ int permcol(int s) {
    return (s < 8) ? ((s & 1) ? 2 * s - 1 : 2 * s)
                   : ((s & 1) ? 2 * s - 15 : 2 * s - 14);
}

// ============================================================
// Kernel 1: Weff^T precompute (angle recurrence)
// ============================================================
__global__ void weff_kernel(const float* __restrict__ weight) {
    __shared__ float w1[129], w2[129];
    const int e = blockIdx.x;
    for (int f = threadIdx.x; f < NFEAT; f += 256) {
        float v = weight[e * NFEAT + f];
        if (f < 129) w1[f] = v; else w2[f - 129] = v;
    }
    __syncthreads();
    const int n = threadIdx.x;                // k position 0..255
    float s1, c1;
    sincospif((float)n / 128.0f, &s1, &c1);   // step angle 2*pi*n/256
    float acc = w1[0];
    float c = c1, s = s1;
    #pragma unroll 4
    for (int kk = 1; kk <= 128; kk++) {
        acc = fmaf(c, w1[kk], acc);
        acc = fmaf(-s, w2[kk], acc);
        float cn = fmaf(c, c1, -s * s1);
        float sn = fmaf(s, c1,  c * s1);
        c = cn; s = sn;
    }
    g_weffT[e * W_SZ + n] = __float2half_rn(acc);
}

// ============================================================
// Kernel 2: persistent GEMM, grid=592 (4 CTAs/SM), 128 threads
// warp tile: 128m x 16n; fp16 accumulators; split-phase mbarrier
// ============================================================
__global__ void __launch_bounds__(THREADS, 4) fft_gemm_kernel(
    const float* __restrict__ x,
    const float* __restrict__ bias,
    float* __restrict__ out)
{
    extern __shared__ char smem[];
    __half* Bs = (__half*)smem;
    float (*seg)[384] = (float(*)[384])(smem + OFF_SEG);
    const uint32_t sb = smem_to_u32(smem);
    const uint32_t mbar = sb + OFF_MBAR;

    const int tid  = threadIdx.x;
    const int wid  = tid >> 5;
    const int lane = tid & 31;
    const int q    = lane & 3;
    const int r4   = lane >> 2;
    const int ng   = (int)(blockIdx.x & (NGROUPS - 1));
    const int e0   = ng * BN;

    if (tid == 0) MBARRIER_INIT(mbar, THREADS);

    // ---- load B tile (WeffT rows e0..e0+63), permuted within slices ----
    for (int u = tid; u < 2048; u += THREADS) {
        int r  = u >> 5;          // Bs row 0..63
        int ch = u & 31;          // 16B chunk along k
        int esrc = e0 + (r & ~15) + permcol(r & 15);
        uint4 v = *reinterpret_cast<const uint4*>(&g_weffT[esrc * W_SZ + ch * 8]);
        *reinterpret_cast<uint4*>(Bs + r * PB + ch * 8) = v;
    }

    // ---- per-thread bias: 4 contiguous cols, packed to fp16 pairs ----
    const int colb = e0 + wid * 16 + 4 * q;
    const float4 bias4 = *reinterpret_cast<const float4*>(bias + colb);
    __half2 hb0 = __floats2half2_rn(bias4.x, bias4.y);
    __half2 hb1 = __floats2half2_rn(bias4.z, bias4.w);
    const uint32_t cb0 = *reinterpret_cast<uint32_t*>(&hb0);
    const uint32_t cb1 = *reinterpret_cast<uint32_t*>(&hb1);

    // ---- ldmatrix base address for this warp's 16-row B slice ----
    const uint32_t sbB = smem_to_u32(Bs);
    const int brow = wid * 16 + (lane & 7) + ((lane & 16) ? 8 : 0);
    const int bkof = (lane & 8) ? 8 : 0;
    const uint32_t baddr0 = sbB + (uint32_t)(brow * PB + bkof) * 2u;

    // ---- initial segment load for first M-tile (383 floats, 128 thr) ----
    const int mt0 = (int)(blockIdx.x >> 3);
    {
        int bidx = mt0 >> 6, t0 = (mt0 & 63) * BM;
        const float* xb = x + bidx * T_SZ;
        #pragma unroll
        for (int c = 0; c < 3; c++) {
            int j = tid + c * 128;
            int gx = t0 + j - (W_SZ - 1);
            if (j < 383) seg[0][j] = (gx >= 0) ? xb[gx] : 0.0f;
        }
    }
    __syncthreads();   // B tile + seg[0] + mbarrier init visible

    int pb = 0, ph = 0;
    for (int mt = mt0; mt < MTILES; mt += CTAS_PER_N, pb ^= 1) {
        // ---- prefetch next segment into registers (all loads guarded) ----
        const int mtn = mt + CTAS_PER_N;
        float p0 = 0.0f, p1 = 0.0f, p2 = 0.0f;
        if (mtn < MTILES) {
            int bidx = mtn >> 6, t0 = (mtn & 63) * BM;
            const float* xb = x + bidx * T_SZ;
            int g0 = t0 + tid - (W_SZ - 1);
            int g1 = g0 + 128;
            int g2 = g0 + 256;
            if (g0 >= 0) p0 = xb[g0];
            if (g1 >= 0) p1 = xb[g1];
            if (tid < 127 && g2 >= 0) p2 = xb[g2];
        }

        // fp16 accumulators: [m][ntile][row01], packed h2 (cols 2q, 2q+1)
        uint32_t acc[8][2][2];
        const float* sg = seg[pb];
        const int base0 = r4 + 2 * q;

        // Toeplitz A: av[j] = half2(seg[base0 + 16*ks + 8j .. +1])
        uint32_t av[17];
        #pragma unroll
        for (int j = 0; j < 17; j++) av[j] = ldcvt(sg + base0 + 8 * j);

        // ---- k-step 0: D = A*B + bias (packed C operand) ----
        {
            uint32_t b0, b1, b2, b3;
            ldmatrix_x4(b0, b1, b2, b3, baddr0);
            #pragma unroll
            for (int m = 0; m < 8; m++) {
                mma16816h_init(acc[m][0], av[2*m], av[2*m+1], av[2*m+1], av[2*m+2],
                               b0, b1, cb0);
                mma16816h_init(acc[m][1], av[2*m], av[2*m+1], av[2*m+1], av[2*m+2],
                               b2, b3, cb1);
            }
            #pragma unroll
            for (int j = 0; j < 15; j++) av[j] = av[j + 2];
            av[15] = ldcvt(sg + base0 + 16 + 120);
            av[16] = ldcvt(sg + base0 + 16 + 128);
        }

        // ---- k-steps 1..15: accumulate in fp16 ----
        #pragma unroll
        for (int ks = 1; ks < 16; ks++) {
            uint32_t b0, b1, b2, b3;
            ldmatrix_x4(b0, b1, b2, b3, baddr0 + (uint32_t)(ks * 32));
            #pragma unroll
            for (int m = 0; m < 8; m++) {
                mma16816h(acc[m][0], av[2*m], av[2*m+1], av[2*m+1], av[2*m+2], b0, b1);
                mma16816h(acc[m][1], av[2*m], av[2*m+1], av[2*m+1], av[2*m+2], b2, b3);
            }
            if (ks < 15) {
                #pragma unroll
                for (int j = 0; j < 15; j++) av[j] = av[j + 2];
                av[15] = ldcvt(sg + base0 + 16 * (ks + 1) + 120);
                av[16] = ldcvt(sg + base0 + 16 * (ks + 1) + 128);
            }
        }

        // ---- store prefetched segment, then ARRIVE (mainloop reads done) ----
        if (mtn < MTILES) {
            seg[pb ^ 1][tid] = p0;
            seg[pb ^ 1][tid + 128] = p1;
            if (tid < 127) seg[pb ^ 1][tid + 256] = p2;
            MBARRIER_ARRIVE(mbar);
        }

        // ---- epilogue (off critical path): unpack h2 -> f32, STG.128 ----
        const size_t rowb = (size_t)mt * BM + (size_t)r4;
        #pragma unroll
        for (int m = 0; m < 8; m++) {
            float* o0 = out + (rowb + 16 * m) * EMB + colb;
            float* o1 = o0 + 8 * EMB;
            float2 e00 = __half22float2(*reinterpret_cast<__half2*>(&acc[m][0][0]));
            float2 e10 = __half22float2(*reinterpret_cast<__half2*>(&acc[m][1][0]));
            float2 e01 = __half22float2(*reinterpret_cast<__half2*>(&acc[m][0][1]));
            float2 e11 = __half22float2(*reinterpret_cast<__half2*>(&acc[m][1][1]));
            float4 v0 = make_float4(e00.x, e00.y, e10.x, e10.y);
            float4 v1 = make_float4(e01.x, e01.y, e11.x, e11.y);
            *reinterpret_cast<float4*>(o0) = v0;
            *reinterpret_cast<float4*>(o1) = v1;
        }

        // ---- wait for all warps' arrivals before next mainloop ----
        if (mtn < MTILES) {
            MBARRIER_WAIT_PARITY(mbar, ph);
            ph ^= 1;
        }
    }
}

// ============================================================
extern "C" void kernel_launch(void* const* d_in, const int* in_sizes, int n_in,
                              void* d_out, int out_size) {
    const float* x  = nullptr;
    const float* wt = nullptr;
    const float* bs = nullptr;
    for (int i = 0; i < n_in; i++) {
        if (in_sizes[i] == B_SZ * T_SZ)        x  = (const float*)d_in[i];
        else if (in_sizes[i] == EMB * NFEAT)   wt = (const float*)d_in[i];
        else if (in_sizes[i] == EMB)           bs = (const float*)d_in[i];
    }

    weff_kernel<<<EMB, 256>>>(wt);

    cudaFuncSetAttribute(fft_gemm_kernel,
                         cudaFuncAttributeMaxDynamicSharedMemorySize, SMEM_TOTAL);
    fft_gemm_kernel<<<GRID, THREADS, SMEM_TOTAL>>>(x, bs, (float*)d_out);
}

// round 16
// speedup vs baseline: 1.1021x; 1.0022x over previous
#include <cuda_runtime.h>
#include <cuda_fp16.h>
#include <cstdint>

// ============================================================
// FFTEmbedding as implicit-im2col GEMM (sm_100 legacy-HMMA path)
//   out = A(131072x256 Toeplitz windows) @ WeffT(512x256)^T + bias
// R16 = R15 (fp16 accumulators, regs 89) + 5 CTAs/SM: grid 736 =
//   8 n-groups x 92, __launch_bounds__(128,5). Fifth independent
//   HMMA stream per SMSP to cut the ~36% tensor-pipe drought.
// ============================================================

#define B_SZ   16
#define T_SZ   8192
#define W_SZ   256
#define EMB    512
#define NFEAT  258

#define BM 128
#define BN 64                 // CTA n-tile
#define MTILES 1024           // (B*T)/BM
#define NGROUPS 8             // EMB/BN
#define GRID   736            // ~5 CTAs per SM (8 x 92)
#define CTAS_PER_N 92         // GRID / NGROUPS
#define THREADS 128

#define PB 264                // B smem pitch in halfs (256 + 8 pad)
#define SMEM_B_BYTES (64 * PB * 2)             // 33792
#define OFF_MBAR  SMEM_B_BYTES                 // 8 bytes + 8 pad
#define OFF_SEG   (SMEM_B_BYTES + 16)
#define SMEM_TOTAL (OFF_SEG + 2 * 384 * 4)

// fp16 Weff^T, [EMB][W_SZ]
__device__ __half g_weffT[EMB * W_SZ];

__device__ __forceinline__ uint32_t smem_to_u32(const void* p) {
    uint32_t a;
    asm("{ .reg .u64 t; cvta.to.shared.u64 t, %1; cvt.u32.u64 %0, t; }" : "=r"(a) : "l"(p));
    return a;
}

__device__ __forceinline__ uint32_t ldcvt(const float* s) {
    __half2 h = __floats2half2_rn(s[0], s[1]);
    return *reinterpret_cast<uint32_t*>(&h);
}

// fp16-accumulate: D(h2 x2) = A*B + D
__device__ __forceinline__ void mma16816h(uint32_t* c, uint32_t a0, uint32_t a1,
                                          uint32_t a2, uint32_t a3,
                                          uint32_t b0, uint32_t b1) {
    asm volatile(
        "mma.sync.aligned.m16n8k16.row.col.f16.f16.f16.f16 "
        "{%0,%1}, {%2,%3,%4,%5}, {%6,%7}, {%0,%1};"
        : "+r"(c[0]), "+r"(c[1])
        : "r"(a0), "r"(a1), "r"(a2), "r"(a3), "r"(b0), "r"(b1));
}

// fp16-accumulate init: D = A*B + {cb, cb}
__device__ __forceinline__ void mma16816h_init(uint32_t* d, uint32_t a0, uint32_t a1,
                                               uint32_t a2, uint32_t a3,
                                               uint32_t b0, uint32_t b1, uint32_t cb) {
    asm volatile(
        "mma.sync.aligned.m16n8k16.row.col.f16.f16.f16.f16 "
        "{%0,%1}, {%2,%3,%4,%5}, {%6,%7}, {%8,%8};"
        : "=r"(d[0]), "=r"(d[1])
        : "r"(a0), "r"(a1), "r"(a2), "r"(a3), "r"(b0), "r"(b1), "r"(cb));
}

__device__ __forceinline__ void ldmatrix_x4(uint32_t& r0, uint32_t& r1,
                                            uint32_t& r2, uint32_t& r3, uint32_t addr) {
    asm volatile("ldmatrix.sync.aligned.m8n8.x4.shared.b16 {%0,%1,%2,%3}, [%4];"
                 : "=r"(r0), "=r"(r1), "=r"(r2), "=r"(r3) : "r"(addr));
}

#define MBARRIER_INIT(addr, count) \
    asm volatile("mbarrier.init.shared.b64 [%0], %1;" \
        :: "r"((uint32_t)(addr)), "r"((uint32_t)(count)) : "memory")

#define MBARRIER_ARRIVE(addr) \
    asm volatile("mbarrier.arrive.release.cta.shared.b64 _, [%0];" \
        :: "r"((uint32_t)(addr)) : "memory")

#define MBARRIER_WAIT_PARITY(mbar_smem_addr, phase_parity) do { \
    uint32_t _mbar = (uint32_t)(mbar_smem_addr); \
    uint32_t _parity = (uint32_t)(phase_parity); \
    uint32_t _done; \
    asm volatile( \
        "{\n\t.reg .pred p;\n\t" \
        "mbarrier.try_wait.parity.acquire.cta.shared::cta.b64 p, [%1], %2;\n\t" \
        "selp.b32 %0, 1, 0, p;\n\t}" \
        : "=r"(_done) : "r"(_mbar), "r"(_parity) : "memory"); \
    if (!_done) { \
        asm volatile( \
            "{\n\t.reg .pred P1;\n\t" \
            "WAIT_LOOP_%=:\n\t" \
            "mbarrier.try_wait.parity.acquire.cta.shared::cta.b64 P1, [%0], %1, 0x989680;\n\t" \
            "@P1 bra.uni WAIT_DONE_%=;\n\t" \
            "bra.uni WAIT_LOOP_%=;\n\t" \
            "WAIT_DONE_%=:\n\t}" \
            :: "r"(_mbar), "r"(_parity) : "memory"); \
    } \
} while(0)

// Column permutation within each warp's 16-col slice (enables STG.128).
__device__ __host__ __forceinline__ int permcol(int s) {
    return (s < 8) ? ((s & 1) ? 2 * s - 1 : 2 * s)
                   : ((s & 1) ? 2 * s - 15 : 2 * s - 14);
}

// ============================================================
// Kernel 1: Weff^T precompute (angle recurrence)
// ============================================================
__global__ void weff_kernel(const float* __restrict__ weight) {
    __shared__ float w1[129], w2[129];
    const int e = blockIdx.x;
    for (int f = threadIdx.x; f < NFEAT; f += 256) {
        float v = weight[e * NFEAT + f];
        if (f < 129) w1[f] = v; else w2[f - 129] = v;
    }
    __syncthreads();
    const int n = threadIdx.x;                // k position 0..255
    float s1, c1;
    sincospif((float)n / 128.0f, &s1, &c1);   // step angle 2*pi*n/256
    float acc = w1[0];
    float c = c1, s = s1;
    #pragma unroll 4
    for (int kk = 1; kk <= 128; kk++) {
        acc = fmaf(c, w1[kk], acc);
        acc = fmaf(-s, w2[kk], acc);
        float cn = fmaf(c, c1, -s * s1);
        float sn = fmaf(s, c1,  c * s1);
        c = cn; s = sn;
    }
    g_weffT[e * W_SZ + n] = __float2half_rn(acc);
}

// ============================================================
// Kernel 2: persistent GEMM, grid=736 (5 CTAs/SM), 128 threads
// warp tile: 128m x 16n; fp16 accumulators; split-phase mbarrier
// ============================================================
__global__ void __launch_bounds__(THREADS, 5) fft_gemm_kernel(
    const float* __restrict__ x,
    const float* __restrict__ bias,
    float* __restrict__ out)
{
    extern __shared__ char smem[];
    __half* Bs = (__half*)smem;
    float (*seg)[384] = (float(*)[384])(smem + OFF_SEG);
    const uint32_t sb = smem_to_u32(smem);
    const uint32_t mbar = sb + OFF_MBAR;

    const int tid  = threadIdx.x;
    const int wid  = tid >> 5;
    const int lane = tid & 31;
    const int q    = lane & 3;
    const int r4   = lane >> 2;
    const int ng   = (int)(blockIdx.x & (NGROUPS - 1));
    const int e0   = ng * BN;

    if (tid == 0) MBARRIER_INIT(mbar, THREADS);

    // ---- load B tile (WeffT rows e0..e0+63), permuted within slices ----
    for (int u = tid; u < 2048; u += THREADS) {
        int r  = u >> 5;          // Bs row 0..63
        int ch = u & 31;          // 16B chunk along k
        int esrc = e0 + (r & ~15) + permcol(r & 15);
        uint4 v = *reinterpret_cast<const uint4*>(&g_weffT[esrc * W_SZ + ch * 8]);
        *reinterpret_cast<uint4*>(Bs + r * PB + ch * 8) = v;
    }

    // ---- per-thread bias: 4 contiguous cols, packed to fp16 pairs ----
    const int colb = e0 + wid * 16 + 4 * q;
    const float4 bias4 = *reinterpret_cast<const float4*>(bias + colb);
    __half2 hb0 = __floats2half2_rn(bias4.x, bias4.y);
    __half2 hb1 = __floats2half2_rn(bias4.z, bias4.w);
    const uint32_t cb0 = *reinterpret_cast<uint32_t*>(&hb0);
    const uint32_t cb1 = *reinterpret_cast<uint32_t*>(&hb1);

    // ---- ldmatrix base address for this warp's 16-row B slice ----
    const uint32_t sbB = smem_to_u32(Bs);
    const int brow = wid * 16 + (lane & 7) + ((lane & 16) ? 8 : 0);
    const int bkof = (lane & 8) ? 8 : 0;
    const uint32_t baddr0 = sbB + (uint32_t)(brow * PB + bkof) * 2u;

    // ---- initial segment load for first M-tile (383 floats, 128 thr) ----
    const int mt0 = (int)(blockIdx.x >> 3);
    {
        int bidx = mt0 >> 6, t0 = (mt0 & 63) * BM;
        const float* xb = x + bidx * T_SZ;
        #pragma unroll
        for (int c = 0; c < 3; c++) {
            int j = tid + c * 128;
            int gx = t0 + j - (W_SZ - 1);
            if (j < 383) seg[0][j] = (gx >= 0) ? xb[gx] : 0.0f;
        }
    }
    __syncthreads();   // B tile + seg[0] + mbarrier init visible

    int pb = 0, ph = 0;
    for (int mt = mt0; mt < MTILES; mt += CTAS_PER_N, pb ^= 1) {
        // ---- prefetch next segment into registers (all loads guarded) ----
        const int mtn = mt + CTAS_PER_N;
        float p0 = 0.0f, p1 = 0.0f, p2 = 0.0f;
        if (mtn < MTILES) {
            int bidx = mtn >> 6, t0 = (mtn & 63) * BM;
            const float* xb = x + bidx * T_SZ;
            int g0 = t0 + tid - (W_SZ - 1);
            int g1 = g0 + 128;
            int g2 = g0 + 256;
            if (g0 >= 0) p0 = xb[g0];
            if (g1 >= 0) p1 = xb[g1];
            if (tid < 127 && g2 >= 0) p2 = xb[g2];
        }

        // fp16 accumulators: [m][ntile][row01], packed h2 (cols 2q, 2q+1)
        uint32_t acc[8][2][2];
        const float* sg = seg[pb];
        const int base0 = r4 + 2 * q;

        // Toeplitz A: av[j] = half2(seg[base0 + 16*ks + 8j .. +1])
        uint32_t av[17];
        #pragma unroll
        for (int j = 0; j < 17; j++) av[j] = ldcvt(sg + base0 + 8 * j);

        // ---- k-step 0: D = A*B + bias (packed C operand) ----
        {
            uint32_t b0, b1, b2, b3;
            ldmatrix_x4(b0, b1, b2, b3, baddr0);
            #pragma unroll
            for (int m = 0; m < 8; m++) {
                mma16816h_init(acc[m][0], av[2*m], av[2*m+1], av[2*m+1], av[2*m+2],
                               b0, b1, cb0);
                mma16816h_init(acc[m][1], av[2*m], av[2*m+1], av[2*m+1], av[2*m+2],
                               b2, b3, cb1);
            }
            #pragma unroll
            for (int j = 0; j < 15; j++) av[j] = av[j + 2];
            av[15] = ldcvt(sg + base0 + 16 + 120);
            av[16] = ldcvt(sg + base0 + 16 + 128);
        }

        // ---- k-steps 1..15: accumulate in fp16 ----
        #pragma unroll
        for (int ks = 1; ks < 16; ks++) {
            uint32_t b0, b1, b2, b3;
            ldmatrix_x4(b0, b1, b2, b3, baddr0 + (uint32_t)(ks * 32));
            #pragma unroll
            for (int m = 0; m < 8; m++) {
                mma16816h(acc[m][0], av[2*m], av[2*m+1], av[2*m+1], av[2*m+2], b0, b1);
                mma16816h(acc[m][1], av[2*m], av[2*m+1], av[2*m+1], av[2*m+2], b2, b3);
            }
            if (ks < 15) {
                #pragma unroll
                for (int j = 0; j < 15; j++) av[j] = av[j + 2];
                av[15] = ldcvt(sg + base0 + 16 * (ks + 1) + 120);
                av[16] = ldcvt(sg + base0 + 16 * (ks + 1) + 128);
            }
        }

        // ---- store prefetched segment, then ARRIVE (mainloop reads done) ----
        if (mtn < MTILES) {
            seg[pb ^ 1][tid] = p0;
            seg[pb ^ 1][tid + 128] = p1;
            if (tid < 127) seg[pb ^ 1][tid + 256] = p2;
            MBARRIER_ARRIVE(mbar);
        }

        // ---- epilogue (off critical path): unpack h2 -> f32, STG.128 ----
        const size_t rowb = (size_t)mt * BM + (size_t)r4;
        #pragma unroll
        for (int m = 0; m < 8; m++) {
            float* o0 = out + (rowb + 16 * m) * EMB + colb;
            float* o1 = o0 + 8 * EMB;
            float2 e00 = __half22float2(*reinterpret_cast<__half2*>(&acc[m][0][0]));
            float2 e10 = __half22float2(*reinterpret_cast<__half2*>(&acc[m][1][0]));
            float2 e01 = __half22float2(*reinterpret_cast<__half2*>(&acc[m][0][1]));
            float2 e11 = __half22float2(*reinterpret_cast<__half2*>(&acc[m][1][1]));
            float4 v0 = make_float4(e00.x, e00.y, e10.x, e10.y);
            float4 v1 = make_float4(e01.x, e01.y, e11.x, e11.y);
            *reinterpret_cast<float4*>(o0) = v0;
            *reinterpret_cast<float4*>(o1) = v1;
        }

        // ---- wait for all warps' arrivals before next mainloop ----
        if (mtn < MTILES) {
            MBARRIER_WAIT_PARITY(mbar, ph);
            ph ^= 1;
        }
    }
}

// ============================================================
extern "C" void kernel_launch(void* const* d_in, const int* in_sizes, int n_in,
                              void* d_out, int out_size) {
    const float* x  = nullptr;
    const float* wt = nullptr;
    const float* bs = nullptr;
    for (int i = 0; i < n_in; i++) {
        if (in_sizes[i] == B_SZ * T_SZ)        x  = (const float*)d_in[i];
        else if (in_sizes[i] == EMB * NFEAT)   wt = (const float*)d_in[i];
        else if (in_sizes[i] == EMB)           bs = (const float*)d_in[i];
    }

    weff_kernel<<<EMB, 256>>>(wt);

    cudaFuncSetAttribute(fft_gemm_kernel,
                         cudaFuncAttributeMaxDynamicSharedMemorySize, SMEM_TOTAL);
    fft_gemm_kernel<<<GRID, THREADS, SMEM_TOTAL>>>(x, bs, (float*)d_out);
}

// round 17
// speedup vs baseline: 1.1097x; 1.0069x over previous
#include <cuda_runtime.h>
#include <cuda_fp16.h>
#include <cstdint>

// ============================================================
// FFTEmbedding as implicit-im2col GEMM (sm_100 legacy-HMMA path)
//   out = A(131072x256 Toeplitz windows) @ WeffT(512x256)^T + bias
// R17 = R16 + software-pipelined B fragments: ldmatrix for k-step
//   ks+1 issues BEFORE the HMMA block of ks (double-buffered bf),
//   removing the ~30-cyc LDSM->HMMA RAW bubble at every k-step head.
// ============================================================

#define B_SZ   16
#define T_SZ   8192
#define W_SZ   256
#define EMB    512
#define NFEAT  258

#define BM 128
#define BN 64                 // CTA n-tile
#define MTILES 1024           // (B*T)/BM
#define NGROUPS 8             // EMB/BN
#define GRID   736            // ~5 CTAs per SM (8 x 92)
#define CTAS_PER_N 92         // GRID / NGROUPS
#define THREADS 128

#define PB 264                // B smem pitch in halfs (256 + 8 pad)
#define SMEM_B_BYTES (64 * PB * 2)             // 33792
#define OFF_MBAR  SMEM_B_BYTES                 // 8 bytes + 8 pad
#define OFF_SEG   (SMEM_B_BYTES + 16)
#define SMEM_TOTAL (OFF_SEG + 2 * 384 * 4)

// fp16 Weff^T, [EMB][W_SZ]
__device__ __half g_weffT[EMB * W_SZ];

__device__ __forceinline__ uint32_t smem_to_u32(const void* p) {
    uint32_t a;
    asm("{ .reg .u64 t; cvta.to.shared.u64 t, %1; cvt.u32.u64 %0, t; }" : "=r"(a) : "l"(p));
    return a;
}

__device__ __forceinline__ uint32_t ldcvt(const float* s) {
    __half2 h = __floats2half2_rn(s[0], s[1]);
    return *reinterpret_cast<uint32_t*>(&h);
}

// fp16-accumulate: D(h2 x2) = A*B + D
__device__ __forceinline__ void mma16816h(uint32_t* c, uint32_t a0, uint32_t a1,
                                          uint32_t a2, uint32_t a3,
                                          uint32_t b0, uint32_t b1) {
    asm volatile(
        "mma.sync.aligned.m16n8k16.row.col.f16.f16.f16.f16 "
        "{%0,%1}, {%2,%3,%4,%5}, {%6,%7}, {%0,%1};"
        : "+r"(c[0]), "+r"(c[1])
        : "r"(a0), "r"(a1), "r"(a2), "r"(a3), "r"(b0), "r"(b1));
}

// fp16-accumulate init: D = A*B + {cb, cb}
__device__ __forceinline__ void mma16816h_init(uint32_t* d, uint32_t a0, uint32_t a1,
                                               uint32_t a2, uint32_t a3,
                                               uint32_t b0, uint32_t b1, uint32_t cb) {
    asm volatile(
        "mma.sync.aligned.m16n8k16.row.col.f16.f16.f16.f16 "
        "{%0,%1}, {%2,%3,%4,%5}, {%6,%7}, {%8,%8};"
        : "=r"(d[0]), "=r"(d[1])
        : "r"(a0), "r"(a1), "r"(a2), "r"(a3), "r"(b0), "r"(b1), "r"(cb));
}

__device__ __forceinline__ void ldmatrix_x4(uint32_t& r0, uint32_t& r1,
                                            uint32_t& r2, uint32_t& r3, uint32_t addr) {
    asm volatile("ldmatrix.sync.aligned.m8n8.x4.shared.b16 {%0,%1,%2,%3}, [%4];"
                 : "=r"(r0), "=r"(r1), "=r"(r2), "=r"(r3) : "r"(addr));
}

#define MBARRIER_INIT(addr, count) \
    asm volatile("mbarrier.init.shared.b64 [%0], %1;" \
        :: "r"((uint32_t)(addr)), "r"((uint32_t)(count)) : "memory")

#define MBARRIER_ARRIVE(addr) \
    asm volatile("mbarrier.arrive.release.cta.shared.b64 _, [%0];" \
        :: "r"((uint32_t)(addr)) : "memory")

#define MBARRIER_WAIT_PARITY(mbar_smem_addr, phase_parity) do { \
    uint32_t _mbar = (uint32_t)(mbar_smem_addr); \
    uint32_t _parity = (uint32_t)(phase_parity); \
    uint32_t _done; \
    asm volatile( \
        "{\n\t.reg .pred p;\n\t" \
        "mbarrier.try_wait.parity.acquire.cta.shared::cta.b64 p, [%1], %2;\n\t" \
        "selp.b32 %0, 1, 0, p;\n\t}" \
        : "=r"(_done) : "r"(_mbar), "r"(_parity) : "memory"); \
    if (!_done) { \
        asm volatile( \
            "{\n\t.reg .pred P1;\n\t" \
            "WAIT_LOOP_%=:\n\t" \
            "mbarrier.try_wait.parity.acquire.cta.shared::cta.b64 P1, [%0], %1, 0x989680;\n\t" \
            "@P1 bra.uni WAIT_DONE_%=;\n\t" \
            "bra.uni WAIT_LOOP_%=;\n\t" \
            "WAIT_DONE_%=:\n\t}" \
            :: "r"(_mbar), "r"(_parity) : "memory"); \
    } \
} while(0)

// Column permutation within each warp's 16-col slice (enables STG.128).
__device__ __host__ __forceinline__ int permcol(int s) {
    return (s < 8) ? ((s & 1) ? 2 * s - 1 : 2 * s)
                   : ((s & 1) ? 2 * s - 15 : 2 * s - 14);
}

// ============================================================
// Kernel 1: Weff^T precompute (angle recurrence)
// ============================================================
__global__ void weff_kernel(const float* __restrict__ weight) {
    __shared__ float w1[129], w2[129];
    const int e = blockIdx.x;
    for (int f = threadIdx.x; f < NFEAT; f += 256) {
        float v = weight[e * NFEAT + f];
        if (f < 129) w1[f] = v; else w2[f - 129] = v;
    }
    __syncthreads();
    const int n = threadIdx.x;                // k position 0..255
    float s1, c1;
    sincospif((float)n / 128.0f, &s1, &c1);   // step angle 2*pi*n/256
    float acc = w1[0];
    float c = c1, s = s1;
    #pragma unroll 4
    for (int kk = 1; kk <= 128; kk++) {
        acc = fmaf(c, w1[kk], acc);
        acc = fmaf(-s, w2[kk], acc);
        float cn = fmaf(c, c1, -s * s1);
        float sn = fmaf(s, c1,  c * s1);
        c = cn; s = sn;
    }
    g_weffT[e * W_SZ + n] = __float2half_rn(acc);
}

// ============================================================
// Kernel 2: persistent GEMM, grid=736 (5 CTAs/SM), 128 threads
// warp tile: 128m x 16n; fp16 accumulators; pipelined B frags
// ============================================================
__global__ void __launch_bounds__(THREADS, 5) fft_gemm_kernel(
    const float* __restrict__ x,
    const float* __restrict__ bias,
    float* __restrict__ out)
{
    extern __shared__ char smem[];
    __half* Bs = (__half*)smem;
    float (*seg)[384] = (float(*)[384])(smem + OFF_SEG);
    const uint32_t sb = smem_to_u32(smem);
    const uint32_t mbar = sb + OFF_MBAR;

    const int tid  = threadIdx.x;
    const int wid  = tid >> 5;
    const int lane = tid & 31;
    const int q    = lane & 3;
    const int r4   = lane >> 2;
    const int ng   = (int)(blockIdx.x & (NGROUPS - 1));
    const int e0   = ng * BN;

    if (tid == 0) MBARRIER_INIT(mbar, THREADS);

    // ---- load B tile (WeffT rows e0..e0+63), permuted within slices ----
    for (int u = tid; u < 2048; u += THREADS) {
        int r  = u >> 5;          // Bs row 0..63
        int ch = u & 31;          // 16B chunk along k
        int esrc = e0 + (r & ~15) + permcol(r & 15);
        uint4 v = *reinterpret_cast<const uint4*>(&g_weffT[esrc * W_SZ + ch * 8]);
        *reinterpret_cast<uint4*>(Bs + r * PB + ch * 8) = v;
    }

    // ---- per-thread bias: 4 contiguous cols, packed to fp16 pairs ----
    const int colb = e0 + wid * 16 + 4 * q;
    const float4 bias4 = *reinterpret_cast<const float4*>(bias + colb);
    __half2 hb0 = __floats2half2_rn(bias4.x, bias4.y);
    __half2 hb1 = __floats2half2_rn(bias4.z, bias4.w);
    const uint32_t cb0 = *reinterpret_cast<uint32_t*>(&hb0);
    const uint32_t cb1 = *reinterpret_cast<uint32_t*>(&hb1);

    // ---- ldmatrix base address for this warp's 16-row B slice ----
    const uint32_t sbB = smem_to_u32(Bs);
    const int brow = wid * 16 + (lane & 7) + ((lane & 16) ? 8 : 0);
    const int bkof = (lane & 8) ? 8 : 0;
    const uint32_t baddr0 = sbB + (uint32_t)(brow * PB + bkof) * 2u;

    // ---- initial segment load for first M-tile (383 floats, 128 thr) ----
    const int mt0 = (int)(blockIdx.x >> 3);
    {
        int bidx = mt0 >> 6, t0 = (mt0 & 63) * BM;
        const float* xb = x + bidx * T_SZ;
        #pragma unroll
        for (int c = 0; c < 3; c++) {
            int j = tid + c * 128;
            int gx = t0 + j - (W_SZ - 1);
            if (j < 383) seg[0][j] = (gx >= 0) ? xb[gx] : 0.0f;
        }
    }
    __syncthreads();   // B tile + seg[0] + mbarrier init visible

    int pb = 0, ph = 0;
    for (int mt = mt0; mt < MTILES; mt += CTAS_PER_N, pb ^= 1) {
        // ---- prefetch next segment into registers (all loads guarded) ----
        const int mtn = mt + CTAS_PER_N;
        float p0 = 0.0f, p1 = 0.0f, p2 = 0.0f;
        if (mtn < MTILES) {
            int bidx = mtn >> 6, t0 = (mtn & 63) * BM;
            const float* xb = x + bidx * T_SZ;
            int g0 = t0 + tid - (W_SZ - 1);
            int g1 = g0 + 128;
            int g2 = g0 + 256;
            if (g0 >= 0) p0 = xb[g0];
            if (g1 >= 0) p1 = xb[g1];
            if (tid < 127 && g2 >= 0) p2 = xb[g2];
        }

        // fp16 accumulators: [m][ntile][row01], packed h2 (cols 2q, 2q+1)
        uint32_t acc[8][2][2];
        const float* sg = seg[pb];
        const int base0 = r4 + 2 * q;

        // Toeplitz A: av[j] = half2(seg[base0 + 16*ks + 8j .. +1])
        uint32_t av[17];
        #pragma unroll
        for (int j = 0; j < 17; j++) av[j] = ldcvt(sg + base0 + 8 * j);

        // double-buffered B fragments; prefill step 0
        uint32_t bf[2][4];
        ldmatrix_x4(bf[0][0], bf[0][1], bf[0][2], bf[0][3], baddr0);

        // ---- k-step 0: prefetch bf[1], then D = A*B + bias ----
        {
            ldmatrix_x4(bf[1][0], bf[1][1], bf[1][2], bf[1][3], baddr0 + 32u);
            #pragma unroll
            for (int m = 0; m < 8; m++) {
                mma16816h_init(acc[m][0], av[2*m], av[2*m+1], av[2*m+1], av[2*m+2],
                               bf[0][0], bf[0][1], cb0);
                mma16816h_init(acc[m][1], av[2*m], av[2*m+1], av[2*m+1], av[2*m+2],
                               bf[0][2], bf[0][3], cb1);
            }
            #pragma unroll
            for (int j = 0; j < 15; j++) av[j] = av[j + 2];
            av[15] = ldcvt(sg + base0 + 16 + 120);
            av[16] = ldcvt(sg + base0 + 16 + 128);
        }

        // ---- k-steps 1..15: LDSM for ks+1 first, then HMMAs of ks ----
        #pragma unroll
        for (int ks = 1; ks < 16; ks++) {
            const int cur = ks & 1;
            if (ks < 15) {
                ldmatrix_x4(bf[cur ^ 1][0], bf[cur ^ 1][1],
                            bf[cur ^ 1][2], bf[cur ^ 1][3],
                            baddr0 + (uint32_t)((ks + 1) * 32));
            }
            #pragma unroll
            for (int m = 0; m < 8; m++) {
                mma16816h(acc[m][0], av[2*m], av[2*m+1], av[2*m+1], av[2*m+2],
                          bf[cur][0], bf[cur][1]);
                mma16816h(acc[m][1], av[2*m], av[2*m+1], av[2*m+1], av[2*m+2],
                          bf[cur][2], bf[cur][3]);
            }
            if (ks < 15) {
                #pragma unroll
                for (int j = 0; j < 15; j++) av[j] = av[j + 2];
                av[15] = ldcvt(sg + base0 + 16 * (ks + 1) + 120);
                av[16] = ldcvt(sg + base0 + 16 * (ks + 1) + 128);
            }
        }

        // ---- store prefetched segment, then ARRIVE (mainloop reads done) ----
        if (mtn < MTILES) {
            seg[pb ^ 1][tid] = p0;
            seg[pb ^ 1][tid + 128] = p1;
            if (tid < 127) seg[pb ^ 1][tid + 256] = p2;
            MBARRIER_ARRIVE(mbar);
        }

        // ---- epilogue (off critical path): unpack h2 -> f32, STG.128 ----
        const size_t rowb = (size_t)mt * BM + (size_t)r4;
        #pragma unroll
        for (int m = 0; m < 8; m++) {
            float* o0 = out + (rowb + 16 * m) * EMB + colb;
            float* o1 = o0 + 8 * EMB;
            float2 e00 = __half22float2(*reinterpret_cast<__half2*>(&acc[m][0][0]));
            float2 e10 = __half22float2(*reinterpret_cast<__half2*>(&acc[m][1][0]));
            float2 e01 = __half22float2(*reinterpret_cast<__half2*>(&acc[m][0][1]));
            float2 e11 = __half22float2(*reinterpret_cast<__half2*>(&acc[m][1][1]));
            float4 v0 = make_float4(e00.x, e00.y, e10.x, e10.y);
            float4 v1 = make_float4(e01.x, e01.y, e11.x, e11.y);
            *reinterpret_cast<float4*>(o0) = v0;
            *reinterpret_cast<float4*>(o1) = v1;
        }

        // ---- wait for all warps' arrivals before next mainloop ----
        if (mtn < MTILES) {
            MBARRIER_WAIT_PARITY(mbar, ph);
            ph ^= 1;
        }
    }
}

// ============================================================
extern "C" void kernel_launch(void* const* d_in, const int* in_sizes, int n_in,
                              void* d_out, int out_size) {
    const float* x  = nullptr;
    const float* wt = nullptr;
    const float* bs = nullptr;
    for (int i = 0; i < n_in; i++) {
        if (in_sizes[i] == B_SZ * T_SZ)        x  = (const float*)d_in[i];
        else if (in_sizes[i] == EMB * NFEAT)   wt = (const float*)d_in[i];
        else if (in_sizes[i] == EMB)           bs = (const float*)d_in[i];
    }

    weff_kernel<<<EMB, 256>>>(wt);

    cudaFuncSetAttribute(fft_gemm_kernel,
                         cudaFuncAttributeMaxDynamicSharedMemorySize, SMEM_TOTAL);
    fft_gemm_kernel<<<GRID, THREADS, SMEM_TOTAL>>>(x, bs, (float*)d_out);
}